// round 4
// baseline (speedup 1.0000x reference)
#include <cuda_runtime.h>

// BaconAdditionReasoner: per-row pipeline
//   Wn = rowwise minmax-norm(W);  a' = a @ Wn1;  b' = b @ Wn2
//   A_i = clamp(1 - a'_i, 1e-6, 1-1e-6);  B_j likewise
//   prod[k] = prod_{i+j=k} max(A_i, B_j)      (== exp(sum log(1-clip(min))) )
//   y[k] = 1 - prod[k];  y /= (sum(y) + 1e-9)
//
// Mask input (d_in[4]) is structurally i+j==k and is hardcoded.

#define THREADS 256
#define EPS_LO 1e-6f
#define EPS_HI (1.0f - 1e-6f)

__global__ void __launch_bounds__(THREADS) bacon_kernel(
    const float* __restrict__ p1, const float* __restrict__ p2,
    const float* __restrict__ W1, const float* __restrict__ W2,
    float* __restrict__ out, int B)
{
    // Normalized weights: rows padded to 12 floats (48B) so each row is two
    // float4 + one float2, 16B-aligned. Broadcast reads -> conflict free.
    __shared__ float Wn[2][10][12];
    // Staging buffer: holds 2560 floats for an input tile, later 4864 floats
    // for the output tile. 256*19 = 4864 floats = 19456 B.
    __shared__ float buf[THREADS * 19];

    const int tid = threadIdx.x;

    // --- per-block weight normalization (uniform, tiny) ---
    if (tid < 20) {
        const float* W = (tid < 10) ? W1 : W2;
        const int m = tid / 10;
        const int r = tid % 10;
        float row[10];
        #pragma unroll
        for (int c = 0; c < 10; ++c) row[c] = W[r * 10 + c];
        float lo = row[0], hi = row[0];
        #pragma unroll
        for (int c = 1; c < 10; ++c) {
            lo = fminf(lo, row[c]);
            hi = fmaxf(hi, row[c]);
        }
        const float inv = 1.0f / (hi - lo + 1e-8f);
        #pragma unroll
        for (int c = 0; c < 10; ++c) Wn[m][r][c] = (row[c] - lo) * inv;
        Wn[m][r][10] = 0.0f;
        Wn[m][r][11] = 0.0f;
    }

    const size_t blockStart = (size_t)blockIdx.x * THREADS;
    const size_t t = blockStart + tid;
    const bool active = (t < (size_t)B);
    const bool full = (blockStart + THREADS) <= (size_t)B;
    const int cnt = full ? THREADS
                         : (blockStart < (size_t)B ? (int)((size_t)B - blockStart) : 0);

    float a[10], b[10];

    // --- stage p1 tile (coalesced float4) ---
    __syncthreads();
    if (full) {
        const float4* src = (const float4*)(p1 + blockStart * 10);
        float4* dst = (float4*)buf;
        #pragma unroll
        for (int it = 0; it < 3; ++it) {
            int i = tid + it * THREADS;
            if (i < THREADS * 10 / 4) dst[i] = src[i];
        }
    } else {
        for (int i = tid; i < cnt * 10; i += THREADS) buf[i] = p1[blockStart * 10 + i];
    }
    __syncthreads();
    if (active) {
        const float2* v = (const float2*)(buf + tid * 10);
        #pragma unroll
        for (int k = 0; k < 5; ++k) { float2 w = v[k]; a[2 * k] = w.x; a[2 * k + 1] = w.y; }
    }
    __syncthreads();

    // --- stage p2 tile ---
    if (full) {
        const float4* src = (const float4*)(p2 + blockStart * 10);
        float4* dst = (float4*)buf;
        #pragma unroll
        for (int it = 0; it < 3; ++it) {
            int i = tid + it * THREADS;
            if (i < THREADS * 10 / 4) dst[i] = src[i];
        }
    } else {
        for (int i = tid; i < cnt * 10; i += THREADS) buf[i] = p2[blockStart * 10 + i];
    }
    __syncthreads();
    if (active) {
        const float2* v = (const float2*)(buf + tid * 10);
        #pragma unroll
        for (int k = 0; k < 5; ++k) { float2 w = v[k]; b[2 * k] = w.x; b[2 * k + 1] = w.y; }
    }
    __syncthreads();   // all reads of buf done before it is reused for output

    if (active) {
        // --- matvecs: ap = a @ Wn[0], bp = b @ Wn[1] ---
        float ap[10], bp[10];
        #pragma unroll
        for (int i = 0; i < 10; ++i) { ap[i] = 0.0f; bp[i] = 0.0f; }
        #pragma unroll
        for (int j = 0; j < 10; ++j) {
            const float aj = a[j];
            const float bj = b[j];
            const float4 wa0 = *(const float4*)&Wn[0][j][0];
            const float4 wa1 = *(const float4*)&Wn[0][j][4];
            const float2 wa2 = *(const float2*)&Wn[0][j][8];
            const float4 wb0 = *(const float4*)&Wn[1][j][0];
            const float4 wb1 = *(const float4*)&Wn[1][j][4];
            const float2 wb2 = *(const float2*)&Wn[1][j][8];
            ap[0] = fmaf(aj, wa0.x, ap[0]);  ap[1] = fmaf(aj, wa0.y, ap[1]);
            ap[2] = fmaf(aj, wa0.z, ap[2]);  ap[3] = fmaf(aj, wa0.w, ap[3]);
            ap[4] = fmaf(aj, wa1.x, ap[4]);  ap[5] = fmaf(aj, wa1.y, ap[5]);
            ap[6] = fmaf(aj, wa1.z, ap[6]);  ap[7] = fmaf(aj, wa1.w, ap[7]);
            ap[8] = fmaf(aj, wa2.x, ap[8]);  ap[9] = fmaf(aj, wa2.y, ap[9]);
            bp[0] = fmaf(bj, wb0.x, bp[0]);  bp[1] = fmaf(bj, wb0.y, bp[1]);
            bp[2] = fmaf(bj, wb0.z, bp[2]);  bp[3] = fmaf(bj, wb0.w, bp[3]);
            bp[4] = fmaf(bj, wb1.x, bp[4]);  bp[5] = fmaf(bj, wb1.y, bp[5]);
            bp[6] = fmaf(bj, wb1.z, bp[6]);  bp[7] = fmaf(bj, wb1.w, bp[7]);
            bp[8] = fmaf(bj, wb2.x, bp[8]);  bp[9] = fmaf(bj, wb2.y, bp[9]);
        }

        // --- A_i = clamp(1 - ap_i); B_j = clamp(1 - bp_j) ---
        float A[10], Bv[10];
        #pragma unroll
        for (int i = 0; i < 10; ++i) {
            A[i]  = fminf(fmaxf(1.0f - ap[i], EPS_LO), EPS_HI);
            Bv[i] = fminf(fmaxf(1.0f - bp[i], EPS_LO), EPS_HI);
        }

        // --- anti-diagonal products: prod[i+j] *= max(A_i, B_j) ---
        float prod[19];
        #pragma unroll
        for (int k = 0; k < 19; ++k) prod[k] = 1.0f;
        #pragma unroll
        for (int i = 0; i < 10; ++i) {
            const float Ai = A[i];
            #pragma unroll
            for (int j = 0; j < 10; ++j) {
                prod[i + j] *= fmaxf(Ai, Bv[j]);
            }
        }

        // --- y = 1 - prod; normalize; stash into shared ---
        float s = 0.0f;
        #pragma unroll
        for (int k = 0; k < 19; ++k) {
            prod[k] = 1.0f - prod[k];
            s += prod[k];
        }
        const float inv = 1.0f / (s + 1e-9f);
        #pragma unroll
        for (int k = 0; k < 19; ++k) buf[tid * 19 + k] = prod[k] * inv;
    }
    __syncthreads();

    // --- coalesced store of the 256x19 output tile ---
    if (full) {
        float4* dst = (float4*)(out + blockStart * 19);
        const float4* src = (const float4*)buf;
        for (int i = tid; i < THREADS * 19 / 4; i += THREADS) dst[i] = src[i];
    } else {
        for (int i = tid; i < cnt * 19; i += THREADS) out[blockStart * 19 + i] = buf[i];
    }
}

extern "C" void kernel_launch(void* const* d_in, const int* in_sizes, int n_in,
                              void* d_out, int out_size) {
    const float* p1 = (const float*)d_in[0];
    const float* p2 = (const float*)d_in[1];
    const float* W1 = (const float*)d_in[2];
    const float* W2 = (const float*)d_in[3];
    // d_in[4] = mask: structurally i+j==k, hardcoded in the kernel.
    float* out = (float*)d_out;

    const int B = in_sizes[0] / 10;
    const int blocks = (B + THREADS - 1) / THREADS;
    bacon_kernel<<<blocks, THREADS>>>(p1, p2, W1, W2, out, B);
}

// round 5
// speedup vs baseline: 1.1139x; 1.1139x over previous
#include <cuda_runtime.h>

// BaconAdditionReasoner:
//   Wn = rowwise minmax-norm(W);  a' = a @ Wn1;  b' = b @ Wn2
//   A_i = clamp(1 - a'_i); B_j = clamp(1 - b'_j)
//   prod[k] = prod_{i+j=k} max(A_i, B_j)   ( == exp(sum log(1-clip(min))) )
//   y[k] = 1 - prod[k];  y /= (sum(y) + 1e-9)
// mask input (d_in[4]) is structurally i+j==k -> hardcoded.

#define THREADS 256
#define EPS_LO 1e-6f
#define EPS_HI (1.0f - 1e-6f)

typedef unsigned long long u64;

__device__ __forceinline__ u64 pk2(float x) {
    u64 r; asm("mov.b64 %0, {%1, %1};" : "=l"(r) : "f"(x)); return r;
}
__device__ __forceinline__ void fma2(u64& d, u64 a, u64 b) {
    asm("fma.rn.f32x2 %0, %1, %2, %0;" : "+l"(d) : "l"(a), "l"(b));
}
__device__ __forceinline__ float2 upk(u64 v) {
    float2 r; asm("mov.b64 {%0, %1}, %2;" : "=f"(r.x), "=f"(r.y) : "l"(v)); return r;
}

__global__ void __launch_bounds__(THREADS, 4) bacon_kernel(
    const float* __restrict__ p1, const float* __restrict__ p2,
    const float* __restrict__ W1, const float* __restrict__ W2,
    float* __restrict__ out, int B)
{
    // Normalized weights, rows padded to 12 floats (48B): two 16B + one 8B
    // aligned chunks per row; broadcast LDS -> conflict free.
    __shared__ float Wn[2][10][12];
    // 5120 floats: p1 tile [0,2560), p2 tile [2560,5120).
    // Reused (after barrier) as the 256x19 output tile [0,4864).
    __shared__ float buf[THREADS * 20];

    const int tid = threadIdx.x;

    // --- per-block weight normalization (uniform, tiny) ---
    if (tid < 20) {
        const float* W = (tid < 10) ? W1 : W2;
        const int m = tid / 10;
        const int r = tid % 10;
        float row[10];
        #pragma unroll
        for (int c = 0; c < 10; ++c) row[c] = W[r * 10 + c];
        float lo = row[0], hi = row[0];
        #pragma unroll
        for (int c = 1; c < 10; ++c) { lo = fminf(lo, row[c]); hi = fmaxf(hi, row[c]); }
        const float inv = 1.0f / (hi - lo + 1e-8f);
        #pragma unroll
        for (int c = 0; c < 10; ++c) Wn[m][r][c] = (row[c] - lo) * inv;
        Wn[m][r][10] = 0.0f;
        Wn[m][r][11] = 0.0f;
    }

    const size_t blockStart = (size_t)blockIdx.x * THREADS;
    const bool full = (blockStart + THREADS) <= (size_t)B;
    const int cnt = full ? THREADS
                         : (blockStart < (size_t)B ? (int)((size_t)B - blockStart) : 0);
    const bool active = tid < cnt;

    // --- stage BOTH input tiles (coalesced float4, loads overlap) ---
    if (full) {
        const float4* s1 = (const float4*)(p1 + blockStart * 10);
        const float4* s2 = (const float4*)(p2 + blockStart * 10);
        float4* d1 = (float4*)buf;
        float4* d2 = (float4*)(buf + THREADS * 10);
        #pragma unroll
        for (int it = 0; it < 3; ++it) {
            int i = tid + it * THREADS;
            if (i < THREADS * 10 / 4) { d1[i] = s1[i]; d2[i] = s2[i]; }
        }
    } else {
        for (int i = tid; i < cnt * 10; i += THREADS) {
            buf[i] = p1[blockStart * 10 + i];
            buf[THREADS * 10 + i] = p2[blockStart * 10 + i];
        }
    }
    __syncthreads();   // sync #1: Wn + both input tiles ready

    float yv[19];
    if (active) {
        float a[10], b[10];
        {
            const float2* va = (const float2*)(buf + tid * 10);
            const float2* vb = (const float2*)(buf + THREADS * 10 + tid * 10);
            #pragma unroll
            for (int k = 0; k < 5; ++k) {
                float2 w = va[k]; a[2 * k] = w.x; a[2 * k + 1] = w.y;
                float2 u = vb[k]; b[2 * k] = u.x; b[2 * k + 1] = u.y;
            }
        }

        // --- packed f32x2 matvecs: ap = a @ Wn[0], bp = b @ Wn[1] ---
        u64 ap01 = 0, ap23 = 0, ap45 = 0, ap67 = 0, ap89 = 0;
        u64 bp01 = 0, bp23 = 0, bp45 = 0, bp67 = 0, bp89 = 0;
        #pragma unroll
        for (int j = 0; j < 10; ++j) {
            const u64 aj2 = pk2(a[j]);
            const u64 bj2 = pk2(b[j]);
            const ulonglong2 wa0 = *(const ulonglong2*)&Wn[0][j][0];  // pairs (0,1),(2,3)
            const ulonglong2 wa1 = *(const ulonglong2*)&Wn[0][j][4];  // pairs (4,5),(6,7)
            const u64        wa2 = *(const u64*)&Wn[0][j][8];         // pair  (8,9)
            const ulonglong2 wb0 = *(const ulonglong2*)&Wn[1][j][0];
            const ulonglong2 wb1 = *(const ulonglong2*)&Wn[1][j][4];
            const u64        wb2 = *(const u64*)&Wn[1][j][8];
            fma2(ap01, aj2, wa0.x); fma2(ap23, aj2, wa0.y);
            fma2(ap45, aj2, wa1.x); fma2(ap67, aj2, wa1.y);
            fma2(ap89, aj2, wa2);
            fma2(bp01, bj2, wb0.x); fma2(bp23, bj2, wb0.y);
            fma2(bp45, bj2, wb1.x); fma2(bp67, bj2, wb1.y);
            fma2(bp89, bj2, wb2);
        }

        // --- A_i = clamp(1 - ap_i); B_j = clamp(1 - bp_j) ---
        float A[10], Bv[10];
        {
            float2 u;
            u = upk(ap01); A[0] = 1.0f - u.x; A[1] = 1.0f - u.y;
            u = upk(ap23); A[2] = 1.0f - u.x; A[3] = 1.0f - u.y;
            u = upk(ap45); A[4] = 1.0f - u.x; A[5] = 1.0f - u.y;
            u = upk(ap67); A[6] = 1.0f - u.x; A[7] = 1.0f - u.y;
            u = upk(ap89); A[8] = 1.0f - u.x; A[9] = 1.0f - u.y;
            u = upk(bp01); Bv[0] = 1.0f - u.x; Bv[1] = 1.0f - u.y;
            u = upk(bp23); Bv[2] = 1.0f - u.x; Bv[3] = 1.0f - u.y;
            u = upk(bp45); Bv[4] = 1.0f - u.x; Bv[5] = 1.0f - u.y;
            u = upk(bp67); Bv[6] = 1.0f - u.x; Bv[7] = 1.0f - u.y;
            u = upk(bp89); Bv[8] = 1.0f - u.x; Bv[9] = 1.0f - u.y;
        }
        #pragma unroll
        for (int i = 0; i < 10; ++i) {
            A[i]  = fminf(fmaxf(A[i],  EPS_LO), EPS_HI);
            Bv[i] = fminf(fmaxf(Bv[i], EPS_LO), EPS_HI);
        }

        // --- anti-diagonal products: prod[i+j] = prod over max(A_i,B_j) ---
        // init from the (i=0) row and (j=9) column -> 81 remaining multiplies
        float prod[19];
        #pragma unroll
        for (int k = 0; k < 10; ++k) prod[k] = fmaxf(A[0], Bv[k]);
        #pragma unroll
        for (int i = 1; i < 10; ++i) prod[9 + i] = fmaxf(A[i], Bv[9]);
        #pragma unroll
        for (int i = 1; i < 10; ++i) {
            const float Ai = A[i];
            #pragma unroll
            for (int j = 0; j < 9; ++j) prod[i + j] *= fmaxf(Ai, Bv[j]);
        }

        // --- y = 1 - prod; normalize ---
        float s = 0.0f;
        #pragma unroll
        for (int k = 0; k < 19; ++k) { yv[k] = 1.0f - prod[k]; s += yv[k]; }
        const float inv = 1.0f / (s + 1e-9f);
        #pragma unroll
        for (int k = 0; k < 19; ++k) yv[k] *= inv;
    }
    __syncthreads();   // sync #2: all input reads done; buf becomes output tile

    if (active) {
        #pragma unroll
        for (int k = 0; k < 19; ++k) buf[tid * 19 + k] = yv[k];
    }
    __syncthreads();   // sync #3: output tile ready

    // --- coalesced store of the 256x19 output tile ---
    if (full) {
        float4* dst = (float4*)(out + blockStart * 19);
        const float4* src = (const float4*)buf;
        for (int i = tid; i < THREADS * 19 / 4; i += THREADS) dst[i] = src[i];
    } else {
        for (int i = tid; i < cnt * 19; i += THREADS) out[blockStart * 19 + i] = buf[i];
    }
}

extern "C" void kernel_launch(void* const* d_in, const int* in_sizes, int n_in,
                              void* d_out, int out_size) {
    const float* p1 = (const float*)d_in[0];
    const float* p2 = (const float*)d_in[1];
    const float* W1 = (const float*)d_in[2];
    const float* W2 = (const float*)d_in[3];
    // d_in[4] = mask: structurally i+j==k, hardcoded.
    float* out = (float*)d_out;

    const int B = in_sizes[0] / 10;
    const int blocks = (B + THREADS - 1) / THREADS;
    bacon_kernel<<<blocks, THREADS>>>(p1, p2, W1, W2, out, B);
}

// round 6
// speedup vs baseline: 1.2412x; 1.1144x over previous
#include <cuda_runtime.h>

// BaconAdditionReasoner:
//   Wn = rowwise minmax-norm(W);  ap = a @ Wn1;  bp = b @ Wn2
//   A_i = clamp(1-ap_i, 1e-6, 1-1e-6); B_j likewise
//   prod[k] = prod_{i+j=k} max(A_i, B_j)   ( == exp(sum log(1-clip(min))) )
//   y[k] = (1 - prod[k]) / (19 - sum(prod) + 1e-9)
// mask input (d_in[4]) is structurally i+j==k -> hardcoded.
//
// Warp-autonomous design: one __syncthreads (weights); each warp stages its
// own 32-row tile, computes, and writes its own output slice.

#define THREADS 128
#define WARPS (THREADS / 32)
#define EPS_LO 1e-6f
#define EPS_HI (1.0f - 1e-6f)

typedef unsigned long long u64;

__device__ __forceinline__ u64 pk2(float x) {
    u64 r; asm("mov.b64 %0, {%1, %1};" : "=l"(r) : "f"(x)); return r;
}
__device__ __forceinline__ void fma2(u64& d, u64 a, u64 b) {
    asm("fma.rn.f32x2 %0, %1, %2, %0;" : "+l"(d) : "l"(a), "l"(b));
}
__device__ __forceinline__ float2 upk(u64 v) {
    float2 r; asm("mov.b64 {%0, %1}, %2;" : "=f"(r.x), "=f"(r.y) : "l"(v)); return r;
}

__global__ void __launch_bounds__(THREADS, 8) bacon_kernel(
    const float* __restrict__ p1, const float* __restrict__ p2,
    const float* __restrict__ W1, const float* __restrict__ W2,
    float* __restrict__ out, int B)
{
    // Packed NEGATED normalized weights. Float view of row j:
    //   [ -Wn1[j][0..9] | -Wn2[j][0..9] ]  (20 floats = 80B, 16B-aligned rows)
    // u64 view: k=0..4 -> W1 pairs (c01,c23,c45,c67,c89), k=5..9 -> W2 pairs.
    __shared__ u64 Wp[10][10];
    // Per-warp slices: 640 floats each (p1 tile 320 | p2 tile 320),
    // reused per-warp (after syncwarp) as the 32x19=608-float output tile.
    __shared__ float sbuf[WARPS * 640];

    const int tid  = threadIdx.x;
    const int wid  = tid >> 5;
    const int lane = tid & 31;

    // --- weight normalization (20 threads; uniform tiny work) ---
    if (tid < 20) {
        const float* W = (tid < 10) ? W1 : W2;
        const int m = tid / 10;
        const int r = tid % 10;
        float row[10];
        #pragma unroll
        for (int c = 0; c < 10; ++c) row[c] = W[r * 10 + c];
        float lo = row[0], hi = row[0];
        #pragma unroll
        for (int c = 1; c < 10; ++c) { lo = fminf(lo, row[c]); hi = fmaxf(hi, row[c]); }
        const float ninv = -1.0f / (hi - lo + 1e-8f);       // negate here
        float* frow = (float*)&Wp[r][0];
        #pragma unroll
        for (int c = 0; c < 10; ++c) frow[m * 10 + c] = (row[c] - lo) * ninv;
    }
    __syncthreads();   // the ONLY block-wide barrier

    const size_t warpStart = (size_t)blockIdx.x * THREADS + (size_t)wid * 32;
    const bool wfull = (warpStart + 32) <= (size_t)B;
    const int wcnt = wfull ? 32
                           : (warpStart < (size_t)B ? (int)((size_t)B - warpStart) : 0);
    const bool active = lane < wcnt;

    float* slice = sbuf + wid * 640;

    // --- per-warp input staging (coalesced float4) ---
    if (wfull) {
        const float4* s1 = (const float4*)(p1 + warpStart * 10);
        const float4* s2 = (const float4*)(p2 + warpStart * 10);
        float4* d1 = (float4*)slice;
        float4* d2 = (float4*)(slice + 320);
        #pragma unroll
        for (int it = 0; it < 3; ++it) {
            int i = lane + it * 32;
            if (i < 80) { d1[i] = s1[i]; d2[i] = s2[i]; }
        }
    } else {
        for (int i = lane; i < wcnt * 10; i += 32) {
            slice[i]       = p1[warpStart * 10 + i];
            slice[320 + i] = p2[warpStart * 10 + i];
        }
    }
    __syncwarp();

    float yv[19];
    if (active) {
        float a[10], b[10];
        {
            const float2* va = (const float2*)(slice + lane * 10);
            const float2* vb = (const float2*)(slice + 320 + lane * 10);
            #pragma unroll
            for (int k = 0; k < 5; ++k) {
                float2 w = va[k]; a[2 * k] = w.x; a[2 * k + 1] = w.y;
                float2 u = vb[k]; b[2 * k] = u.x; b[2 * k + 1] = u.y;
            }
        }

        // --- packed matvecs with negated weights, acc init 1.0:
        //     A_raw = 1 - a @ Wn1,  B_raw = 1 - b @ Wn2
        const u64 ONE2 = pk2(1.0f);
        u64 A01 = ONE2, A23 = ONE2, A45 = ONE2, A67 = ONE2, A89 = ONE2;
        u64 B01 = ONE2, B23 = ONE2, B45 = ONE2, B67 = ONE2, B89 = ONE2;
        #pragma unroll
        for (int j = 0; j < 10; ++j) {
            const u64 aj2 = pk2(a[j]);
            const u64 bj2 = pk2(b[j]);
            const ulonglong2* wr = (const ulonglong2*)&Wp[j][0];
            const ulonglong2 q0 = wr[0];   // W1 pairs c01, c23
            const ulonglong2 q1 = wr[1];   // W1 pairs c45, c67
            const ulonglong2 q2 = wr[2];   // W1 pair c89 | W2 pair c01
            const ulonglong2 q3 = wr[3];   // W2 pairs c23, c45
            const ulonglong2 q4 = wr[4];   // W2 pairs c67, c89
            fma2(A01, aj2, q0.x); fma2(A23, aj2, q0.y);
            fma2(A45, aj2, q1.x); fma2(A67, aj2, q1.y);
            fma2(A89, aj2, q2.x);
            fma2(B01, bj2, q2.y); fma2(B23, bj2, q3.x);
            fma2(B45, bj2, q3.y); fma2(B67, bj2, q4.x);
            fma2(B89, bj2, q4.y);
        }

        // --- clamp to [1e-6, 1-1e-6] ---
        float A[10], Bv[10];
        {
            float2 u;
            u = upk(A01); A[0] = u.x; A[1] = u.y;
            u = upk(A23); A[2] = u.x; A[3] = u.y;
            u = upk(A45); A[4] = u.x; A[5] = u.y;
            u = upk(A67); A[6] = u.x; A[7] = u.y;
            u = upk(A89); A[8] = u.x; A[9] = u.y;
            u = upk(B01); Bv[0] = u.x; Bv[1] = u.y;
            u = upk(B23); Bv[2] = u.x; Bv[3] = u.y;
            u = upk(B45); Bv[4] = u.x; Bv[5] = u.y;
            u = upk(B67); Bv[6] = u.x; Bv[7] = u.y;
            u = upk(B89); Bv[8] = u.x; Bv[9] = u.y;
        }
        #pragma unroll
        for (int i = 0; i < 10; ++i) {
            A[i]  = fminf(fmaxf(A[i],  EPS_LO), EPS_HI);
            Bv[i] = fminf(fmaxf(Bv[i], EPS_LO), EPS_HI);
        }

        // --- anti-diagonal products: prod[i+j] = prod over max(A_i,B_j)
        //     init from i=0 row and j=9 column -> 81 remaining multiplies
        float prod[19];
        #pragma unroll
        for (int k = 0; k < 10; ++k) prod[k] = fmaxf(A[0], Bv[k]);
        #pragma unroll
        for (int i = 1; i < 10; ++i) prod[9 + i] = fmaxf(A[i], Bv[9]);
        #pragma unroll
        for (int i = 1; i < 10; ++i) {
            const float Ai = A[i];
            #pragma unroll
            for (int j = 0; j < 9; ++j) prod[i + j] *= fmaxf(Ai, Bv[j]);
        }

        // --- y[k] = (1 - prod[k]) * inv,  inv = 1/(19 - sum(prod) + 1e-9)
        float sp = 0.0f;
        #pragma unroll
        for (int k = 0; k < 19; ++k) sp += prod[k];
        const float inv = __fdividef(1.0f, (19.0f - sp) + 1e-9f);
        #pragma unroll
        for (int k = 0; k < 19; ++k) yv[k] = fmaf(-prod[k], inv, inv);
    }
    __syncwarp();   // all input reads done; slice becomes output tile

    if (active) {
        #pragma unroll
        for (int k = 0; k < 19; ++k) slice[lane * 19 + k] = yv[k];
    }
    __syncwarp();

    // --- per-warp coalesced store of its 32x19 output tile ---
    if (wfull) {
        float4* dst = (float4*)(out + warpStart * 19);
        const float4* src = (const float4*)slice;
        #pragma unroll
        for (int it = 0; it < 5; ++it) {
            int i = lane + it * 32;
            if (i < 152) dst[i] = src[i];
        }
    } else {
        for (int i = lane; i < wcnt * 19; i += 32) out[warpStart * 19 + i] = slice[i];
    }
}

extern "C" void kernel_launch(void* const* d_in, const int* in_sizes, int n_in,
                              void* d_out, int out_size) {
    const float* p1 = (const float*)d_in[0];
    const float* p2 = (const float*)d_in[1];
    const float* W1 = (const float*)d_in[2];
    const float* W2 = (const float*)d_in[3];
    // d_in[4] = mask: structurally i+j==k, hardcoded.
    float* out = (float*)d_out;

    const int B = in_sizes[0] / 10;
    const int blocks = (B + THREADS - 1) / THREADS;
    bacon_kernel<<<blocks, THREADS>>>(p1, p2, W1, W2, out, B);
}

// round 7
// speedup vs baseline: 1.4312x; 1.1530x over previous
#include <cuda_runtime.h>

// BaconAdditionReasoner:
//   Wn = rowwise minmax-norm(W);  ap = a @ Wn1;  bp = b @ Wn2
//   A_i = clamp(1-ap_i, 1e-6, 1-1e-6); B_j likewise
//   prod[k] = prod_{i+j=k} max(A_i, B_j)   ( == exp(sum log(1-clip(min))) )
//   y[k] = (1 - prod[k]) / (19 - sum(prod) + 1e-9)
// mask input (d_in[4]) is structurally i+j==k -> hardcoded.
//
// 2 elements/thread: each warp owns 64 rows, lane handles rows lane and
// lane+32, sharing all weight-row LDS between the two elements. Matvec is
// phase-split (W1 pass then W2 pass) to cap register pressure.

#define THREADS 128
#define WARPS (THREADS / 32)
#define ROWS_PER_WARP 64
#define ROWS_PER_BLOCK (THREADS * 2)
#define EPS_LO 1e-6f
#define EPS_HI (1.0f - 1e-6f)

typedef unsigned long long u64;

__device__ __forceinline__ u64 pk2(float x) {
    u64 r; asm("mov.b64 %0, {%1, %1};" : "=l"(r) : "f"(x)); return r;
}
__device__ __forceinline__ void fma2(u64& d, u64 a, u64 b) {
    asm("fma.rn.f32x2 %0, %1, %2, %0;" : "+l"(d) : "l"(a), "l"(b));
}
__device__ __forceinline__ float2 upk(u64 v) {
    float2 r; asm("mov.b64 {%0, %1}, %2;" : "=f"(r.x), "=f"(r.y) : "l"(v)); return r;
}
__device__ __forceinline__ float clampP(float x) {
    return fminf(fmaxf(x, EPS_LO), EPS_HI);
}

// acc holds 1 - p@Wn (weights pre-negated, acc init 1.0); unpack + clamp.
__device__ __forceinline__ void unpack_clamp(const u64* acc, float* A) {
    #pragma unroll
    for (int t = 0; t < 5; ++t) {
        float2 u = upk(acc[t]);
        A[2 * t]     = clampP(u.x);
        A[2 * t + 1] = clampP(u.y);
    }
}

// prod[k] = prod_{i+j=k} max(A_i,B_j); y = (1-prod)/(19-sum+1e-9) -> dst[0..18]
__device__ __forceinline__ void epilogue(const float* A, const float* Bv, float* dst) {
    float prod[19];
    #pragma unroll
    for (int k = 0; k < 10; ++k) prod[k] = fmaxf(A[0], Bv[k]);
    #pragma unroll
    for (int i = 1; i < 10; ++i) prod[9 + i] = fmaxf(A[i], Bv[9]);
    #pragma unroll
    for (int i = 1; i < 10; ++i) {
        const float Ai = A[i];
        #pragma unroll
        for (int j = 0; j < 9; ++j) prod[i + j] *= fmaxf(Ai, Bv[j]);
    }
    float sp = 0.0f;
    #pragma unroll
    for (int k = 0; k < 19; ++k) sp += prod[k];
    const float inv = __fdividef(1.0f, (19.0f - sp) + 1e-9f);
    #pragma unroll
    for (int k = 0; k < 19; ++k) dst[k] = fmaf(-prod[k], inv, inv);
}

__global__ void __launch_bounds__(THREADS, 6) bacon_kernel(
    const float* __restrict__ p1, const float* __restrict__ p2,
    const float* __restrict__ W1, const float* __restrict__ W2,
    float* __restrict__ out, int B)
{
    // NEGATED normalized weights; row = 5 u64 pairs, padded to 6 (48B) so
    // pairs (c01,c23) and (c45,c67) are 16B-aligned for LDS.128 broadcast.
    __shared__ u64 Wp1[10][6];
    __shared__ u64 Wp2[10][6];
    // Per-warp slice: 1280 floats = p1 tile [0,640) | p2 tile [640,1280).
    // Reused (after syncwarp) as the 64x19=1216-float output tile.
    __shared__ float sbuf[WARPS * 1280];

    const int tid  = threadIdx.x;
    const int wid  = tid >> 5;
    const int lane = tid & 31;

    // --- weight normalization (20 threads; tiny uniform work) ---
    if (tid < 20) {
        const float* W = (tid < 10) ? W1 : W2;
        const int m = tid / 10;
        const int r = tid % 10;
        float row[10];
        #pragma unroll
        for (int c = 0; c < 10; ++c) row[c] = W[r * 10 + c];
        float lo = row[0], hi = row[0];
        #pragma unroll
        for (int c = 1; c < 10; ++c) { lo = fminf(lo, row[c]); hi = fmaxf(hi, row[c]); }
        const float ninv = -1.0f / (hi - lo + 1e-8f);      // negate here
        float* frow = m ? (float*)&Wp2[r][0] : (float*)&Wp1[r][0];
        #pragma unroll
        for (int c = 0; c < 10; ++c) frow[c] = (row[c] - lo) * ninv;
    }
    __syncthreads();   // the ONLY block-wide barrier

    const size_t warpStart = (size_t)blockIdx.x * ROWS_PER_BLOCK
                           + (size_t)wid * ROWS_PER_WARP;
    const bool wfull = (warpStart + ROWS_PER_WARP) <= (size_t)B;
    float* slice = sbuf + wid * 1280;

    // --- stage 64 rows of p1 and p2 (coalesced float4, streaming) ---
    if (wfull) {
        const float4* s1 = (const float4*)(p1 + warpStart * 10);   // 160 float4
        const float4* s2 = (const float4*)(p2 + warpStart * 10);
        float4* d1 = (float4*)slice;
        float4* d2 = (float4*)(slice + 640);
        #pragma unroll
        for (int it = 0; it < 5; ++it) {
            const int i = lane + it * 32;
            d1[i] = __ldcs(&s1[i]);
            d2[i] = __ldcs(&s2[i]);
        }
    } else {
        const int rows = (warpStart < (size_t)B) ? (int)((size_t)B - warpStart) : 0;
        for (int i = lane; i < 1280; i += 32) slice[i] = 0.0f;  // defined garbage
        __syncwarp();
        for (int i = lane; i < rows * 10; i += 32) {
            slice[i]       = p1[warpStart * 10 + i];
            slice[640 + i] = p2[warpStart * 10 + i];
        }
    }
    __syncwarp();

    const u64 ONE2 = pk2(1.0f);
    float A0[10], A1[10], B0v[10], B1v[10];

    // ---------- Phase A: A = clamp(1 - a @ Wn1) for both elements ----------
    {
        float a0[10], a1[10];
        {
            const float2* v0 = (const float2*)(slice + lane * 10);
            const float2* v1 = (const float2*)(slice + (lane + 32) * 10);
            #pragma unroll
            for (int k = 0; k < 5; ++k) {
                float2 w = v0[k]; a0[2 * k] = w.x; a0[2 * k + 1] = w.y;
                float2 u = v1[k]; a1[2 * k] = u.x; a1[2 * k + 1] = u.y;
            }
        }
        u64 c0[5], c1[5];
        #pragma unroll
        for (int t = 0; t < 5; ++t) { c0[t] = ONE2; c1[t] = ONE2; }
        #pragma unroll
        for (int j = 0; j < 10; ++j) {
            const ulonglong2* wr = (const ulonglong2*)&Wp1[j][0];
            const ulonglong2 q0 = wr[0];           // pairs c01, c23
            const ulonglong2 q1 = wr[1];           // pairs c45, c67
            const u64        q2 = Wp1[j][4];       // pair  c89
            const u64 x0 = pk2(a0[j]);
            const u64 x1 = pk2(a1[j]);
            fma2(c0[0], x0, q0.x); fma2(c0[1], x0, q0.y);
            fma2(c0[2], x0, q1.x); fma2(c0[3], x0, q1.y); fma2(c0[4], x0, q2);
            fma2(c1[0], x1, q0.x); fma2(c1[1], x1, q0.y);
            fma2(c1[2], x1, q1.x); fma2(c1[3], x1, q1.y); fma2(c1[4], x1, q2);
        }
        unpack_clamp(c0, A0);
        unpack_clamp(c1, A1);
    }

    // ---------- Phase B: B = clamp(1 - b @ Wn2) for both elements ----------
    {
        float b0[10], b1[10];
        {
            const float2* v0 = (const float2*)(slice + 640 + lane * 10);
            const float2* v1 = (const float2*)(slice + 640 + (lane + 32) * 10);
            #pragma unroll
            for (int k = 0; k < 5; ++k) {
                float2 w = v0[k]; b0[2 * k] = w.x; b0[2 * k + 1] = w.y;
                float2 u = v1[k]; b1[2 * k] = u.x; b1[2 * k + 1] = u.y;
            }
        }
        u64 c0[5], c1[5];
        #pragma unroll
        for (int t = 0; t < 5; ++t) { c0[t] = ONE2; c1[t] = ONE2; }
        #pragma unroll
        for (int j = 0; j < 10; ++j) {
            const ulonglong2* wr = (const ulonglong2*)&Wp2[j][0];
            const ulonglong2 q0 = wr[0];
            const ulonglong2 q1 = wr[1];
            const u64        q2 = Wp2[j][4];
            const u64 x0 = pk2(b0[j]);
            const u64 x1 = pk2(b1[j]);
            fma2(c0[0], x0, q0.x); fma2(c0[1], x0, q0.y);
            fma2(c0[2], x0, q1.x); fma2(c0[3], x0, q1.y); fma2(c0[4], x0, q2);
            fma2(c1[0], x1, q0.x); fma2(c1[1], x1, q0.y);
            fma2(c1[2], x1, q1.x); fma2(c1[3], x1, q1.y); fma2(c1[4], x1, q2);
        }
        unpack_clamp(c0, B0v);
        unpack_clamp(c1, B1v);
    }
    __syncwarp();   // all slice reads done; slice becomes output tile

    // ---------- epilogues: write both 19-float rows into the slice ----------
    {
        float y0[19], y1[19];
        epilogue(A0, B0v, y0);
        epilogue(A1, B1v, y1);
        #pragma unroll
        for (int k = 0; k < 19; ++k) slice[lane * 19 + k] = y0[k];
        #pragma unroll
        for (int k = 0; k < 19; ++k) slice[(lane + 32) * 19 + k] = y1[k];
    }
    __syncwarp();

    // ---------- coalesced store of the 64x19 output tile ----------
    if (wfull) {
        float4* dst = (float4*)(out + warpStart * 19);
        const float4* src = (const float4*)slice;
        #pragma unroll
        for (int it = 0; it < 10; ++it) {
            const int i = lane + it * 32;
            if (i < 304) __stcs(&dst[i], src[i]);     // 64*19/4 = 304
        }
    } else {
        const int rows = (warpStart < (size_t)B) ? (int)((size_t)B - warpStart) : 0;
        for (int i = lane; i < rows * 19; i += 32) out[warpStart * 19 + i] = slice[i];
    }
}

extern "C" void kernel_launch(void* const* d_in, const int* in_sizes, int n_in,
                              void* d_out, int out_size) {
    const float* p1 = (const float*)d_in[0];
    const float* p2 = (const float*)d_in[1];
    const float* W1 = (const float*)d_in[2];
    const float* W2 = (const float*)d_in[3];
    // d_in[4] = mask: structurally i+j==k, hardcoded.
    float* out = (float*)d_out;

    const int B = in_sizes[0] / 10;
    const int blocks = (B + ROWS_PER_BLOCK - 1) / ROWS_PER_BLOCK;
    bacon_kernel<<<blocks, THREADS>>>(p1, p2, W1, W2, out, B);
}